// round 10
// baseline (speedup 1.0000x reference)
#include <cuda_runtime.h>
#include <cuda_fp16.h>
#include <math.h>
#include <cstdint>

// ---------------------------------------------------------------------------
// Problem constants
// ---------------------------------------------------------------------------
#define B_   1024
#define D_   1024
#define H4   4096
#define BAR_ 32
#define EPS_ 1e-5f

#define SMEM_SWIZZLE_128B(byte_offset) \
    ((byte_offset) ^ (((byte_offset) >> 3) & 0x70))

__device__ __forceinline__ uint32_t smem_to_u32(const void* smem_ptr) {
    uint32_t addr;
    asm("{ .reg .u64 tmp; cvta.to.shared.u64 tmp, %1; cvt.u32.u64 %0, tmp; }"
        : "=r"(addr) : "l"(smem_ptr));
    return addr;
}

__device__ __forceinline__ void ldsm_x4(uint32_t& r0, uint32_t& r1,
                                        uint32_t& r2, uint32_t& r3, uint32_t addr) {
    asm volatile("ldmatrix.sync.aligned.m8n8.x4.shared.b16 {%0,%1,%2,%3}, [%4];"
                 : "=r"(r0), "=r"(r1), "=r"(r2), "=r"(r3) : "r"(addr));
}

__device__ __forceinline__ void mma_fp16(float& d0, float& d1, float& d2, float& d3,
                                         uint32_t a0, uint32_t a1, uint32_t a2, uint32_t a3,
                                         uint32_t b0, uint32_t b1) {
    asm volatile(
        "mma.sync.aligned.m16n8k16.row.col.f32.f16.f16.f32 "
        "{%0,%1,%2,%3}, {%4,%5,%6,%7}, {%8,%9}, {%0,%1,%2,%3};"
        : "+f"(d0), "+f"(d1), "+f"(d2), "+f"(d3)
        : "r"(a0), "r"(a1), "r"(a2), "r"(a3), "r"(b0), "r"(b1));
}

__device__ __forceinline__ void cp_async16(uint32_t dst, const void* src) {
    asm volatile("cp.async.cg.shared.global [%0], [%1], 16;"
                 :: "r"(dst), "l"(src) : "memory");
}
#define CP_COMMIT() asm volatile("cp.async.commit_group;" ::: "memory")
#define CP_WAIT(N)  asm volatile("cp.async.wait_group %0;" :: "n"(N) : "memory")

__device__ __forceinline__ float sigmoidf_(float x) {
    return 1.f / (1.f + expf(-x));
}

// ---------------------------------------------------------------------------
// Scratch (device globals). h-states ping-pong across launches (race fix R8).
// ---------------------------------------------------------------------------
__device__ __half g_znh [B_ * D_];
__device__ __half g_h0a [B_ * D_];
__device__ __half g_h0b [B_ * D_];
__device__ __half g_h1a [B_ * D_];
__device__ __half g_h1b [B_ * D_];
__device__ float  g_c0  [B_ * D_];
__device__ float  g_c1  [B_ * D_];
__device__ float  g_x0p [B_ * H4];
__device__ __half g_feats[(size_t)B_ * BAR_ * D_];
__device__ float  g_scale[D_];
__device__ float  g_shift[D_];
__device__ float  g_b0i [H4];
__device__ float  g_b1i [H4];
__device__ __half g_wih0[H4 * D_];
__device__ __half g_whh0[H4 * D_];
__device__ __half g_wih1[H4 * D_];
__device__ __half g_whh1[H4 * D_];
__device__ __half g_wlin[D_ * D_];

// ---------------------------------------------------------------------------
// Prep kernels (unchanged from R8)
// ---------------------------------------------------------------------------
__global__ void bn_stats_kernel(const float* __restrict__ z,
                                const float* __restrict__ gamma,
                                const float* __restrict__ beta) {
    __shared__ float ssum[8][32];
    __shared__ float ssq [8][32];
    int col = blockIdx.x * 32 + threadIdx.x;
    float s = 0.f, q = 0.f;
    for (int r = threadIdx.y; r < B_; r += 8) {
        float v = z[(size_t)r * D_ + col];
        s += v; q += v * v;
    }
    ssum[threadIdx.y][threadIdx.x] = s;
    ssq [threadIdx.y][threadIdx.x] = q;
    __syncthreads();
    if (threadIdx.y == 0) {
#pragma unroll
        for (int y = 1; y < 8; y++) { s += ssum[y][threadIdx.x]; q += ssq[y][threadIdx.x]; }
        float mean = s * (1.f / (float)B_);
        float var  = q * (1.f / (float)B_) - mean * mean;
        float sc   = gamma[col] * rsqrtf(var + EPS_);
        g_scale[col] = sc;
        g_shift[col] = beta[col] - mean * sc;
    }
}

__global__ void bn_apply_init_kernel(const float* __restrict__ z) {
    int idx = blockIdx.x * blockDim.x + threadIdx.x;
    int col = idx & (D_ - 1);
    float v = z[idx] * g_scale[col] + g_shift[col];
    __half vh = __float2half_rn(v);
    g_znh[idx] = vh;
    g_h0a[idx] = vh; g_h1a[idx] = vh;
    float vr = __half2float(vh);
    g_c0[idx] = vr;  g_c1[idx] = vr;
}

__global__ void bias_interleave_kernel(const float* __restrict__ b_ih0,
                                       const float* __restrict__ b_hh0,
                                       const float* __restrict__ b_ih1,
                                       const float* __restrict__ b_hh1) {
    int j = blockIdx.x * blockDim.x + threadIdx.x;
    if (j < H4) {
        int g = j & 3, h = j >> 2;
        g_b0i[j] = b_ih0[g * D_ + h] + b_hh0[g * D_ + h];
        g_b1i[j] = b_ih1[g * D_ + h] + b_hh1[g * D_ + h];
    }
}

__global__ void weight_interleave_kernel(const float* __restrict__ src,
                                         __half* __restrict__ dst) {
    int j = blockIdx.x * blockDim.x + threadIdx.x;
    int nr = j >> 8;
    int k4 = j & 255;
    int r_old = (nr & 3) * D_ + (nr >> 2);
    float4 v = *(const float4*)(src + (size_t)r_old * D_ + k4 * 4);
    __half2* d = (__half2*)(dst + (size_t)nr * D_ + k4 * 4);
    d[0] = __floats2half2_rn(v.x, v.y);
    d[1] = __floats2half2_rn(v.z, v.w);
}

__global__ void weight_fp16_kernel(const float* __restrict__ src,
                                   __half* __restrict__ dst, int n4) {
    int i = blockIdx.x * blockDim.x + threadIdx.x;
    if (i < n4) {
        float4 v = ((const float4*)src)[i];
        __half2* d = (__half2*)(dst + (size_t)i * 4);
        d[0] = __floats2half2_rn(v.x, v.y);
        d[1] = __floats2half2_rn(v.z, v.w);
    }
}

// ---------------------------------------------------------------------------
// fp16 mma.sync GEMM, CTA tile 128x256, K-chunk 64. 8 warps (2Mx4N), warp
// tile 64x64. ldmatrix.x4 fragment loads, 3-stage cp.async pipeline,
// one __syncthreads per chunk.
// MODE 0: Cout(fp32) = bias? + Cinit? + A1@B1^T (+A2@B2^T)
// MODE 1: fused LSTM cell epilogue (gate-interleaved cols; hout != A1/A2!)
// smem per stage: A 16KB @ +0, B 32KB @ +16K; stage stride 48KB; 3 stages.
// ---------------------------------------------------------------------------
#define TK_ 64
#define STAGE_BYTES 49152u
#define DYN_BYTES (3u * 49152u + 1024u)

template<int MODE>
__global__ __launch_bounds__(256, 1)
void gemm_mma_kernel(const __half* __restrict__ A1, const __half* __restrict__ B1, int K1,
                     const __half* __restrict__ A2, const __half* __restrict__ B2, int K2,
                     const float* __restrict__ Cinit, const float* __restrict__ bias,
                     float* __restrict__ Cout, int Nfull,
                     float* __restrict__ cstate, __half* __restrict__ hout,
                     __half* __restrict__ feats, int t) {
    extern __shared__ char dyn_smem[];
    uint32_t raw  = smem_to_u32(dyn_smem);
    uint32_t base = (raw + 1023u) & ~1023u;

    const int tid  = threadIdx.x;
    const int wid  = tid >> 5;
    const int lane = tid & 31;
    const int lg   = lane >> 2;
    const int lt   = lane & 3;
    const int wm   = wid >> 2;          // 0..1 (M)
    const int wn   = wid & 3;           // 0..3 (N)
    const int row0 = blockIdx.y * 128;
    const int col0 = blockIdx.x * 256;
    const int m0   = wm * 64;
    const int n0   = wn * 64;

    // ldmatrix lane decomposition: i = row-in-8x8, jm = m/n half, jk = k half
    const uint32_t li   = lane & 7;
    const uint32_t jm8  = ((lane >> 3) & 1) * 8;
    const uint32_t jk16 = (lane >> 4) * 16;
    const uint32_t i16  = li << 4;
    // lane-constant row-byte bases (swizzle XOR uses row&7 == li)
    const uint32_t aRow = (uint32_t)(m0 + jm8 + li) * 128;
    const uint32_t bRow = (uint32_t)(n0 + jm8 + li) * 128;

    float acc[4][8][4];
#pragma unroll
    for (int mi = 0; mi < 4; mi++)
#pragma unroll
        for (int nf = 0; nf < 8; nf++)
#pragma unroll
            for (int r = 0; r < 4; r++) acc[mi][nf][r] = 0.f;

    const int nk = (K1 + K2) / TK_;

    auto load_chunk = [&](int kc, int st) {
        const __half* Ag; const __half* Bg; int kk, ldk;
        int k0 = kc * TK_;
        if (k0 < K1) { Ag = A1; Bg = B1; kk = k0;      ldk = K1; }
        else         { Ag = A2; Bg = B2; kk = k0 - K1; ldk = K2; }
        uint32_t sa = base + (uint32_t)st * STAGE_BYTES;
        uint32_t sb = sa + 16384u;
        // A: 128 rows x 8 float4 = 1024; 4 per thread
        {
            int r = tid >> 1;                          // 0..127
            int c0 = (tid & 1) * 4;                    // 0 or 4
#pragma unroll
            for (int j = 0; j < 4; j++) {
                int c = c0 + j;
                cp_async16(sa + SMEM_SWIZZLE_128B(r * 128 + c * 16),
                           Ag + (size_t)(row0 + r) * ldk + kk + c * 8);
            }
        }
        // B: 256 rows x 8 float4 = 2048; 8 per thread
        {
            int r = tid;                               // 0..255
#pragma unroll
            for (int c = 0; c < 8; c++) {
                cp_async16(sb + SMEM_SWIZZLE_128B(r * 128 + c * 16),
                           Bg + (size_t)(col0 + r) * ldk + kk + c * 8);
            }
        }
        CP_COMMIT();
    };

    load_chunk(0, 0);
    if (nk > 1) load_chunk(1, 1);

    for (int k = 0; k < nk; k++) {
        if (k + 1 < nk) { CP_WAIT(1); } else { CP_WAIT(0); }
        __syncthreads();
        if (k + 2 < nk) load_chunk(k + 2, (k + 2) % 3);

        uint32_t sa = base + (uint32_t)(k % 3) * STAGE_BYTES;
        uint32_t sb = sa + 16384u;
#pragma unroll
        for (int ks = 0; ks < 4; ks++) {
            uint32_t kcol = ((uint32_t)(ks * 32) + jk16) ^ i16;
            uint32_t a[4][4];
#pragma unroll
            for (int mi = 0; mi < 4; mi++)
                ldsm_x4(a[mi][0], a[mi][1], a[mi][2], a[mi][3],
                        sa + aRow + (uint32_t)mi * 2048 + kcol);
            uint32_t b[4][4];
#pragma unroll
            for (int ni2 = 0; ni2 < 4; ni2++)
                ldsm_x4(b[ni2][0], b[ni2][1], b[ni2][2], b[ni2][3],
                        sb + bRow + (uint32_t)ni2 * 2048 + kcol);
#pragma unroll
            for (int mi = 0; mi < 4; mi++)
#pragma unroll
                for (int nf = 0; nf < 8; nf++)
                    mma_fp16(acc[mi][nf][0], acc[mi][nf][1],
                             acc[mi][nf][2], acc[mi][nf][3],
                             a[mi][0], a[mi][1], a[mi][2], a[mi][3],
                             b[nf >> 1][nf & 1], b[nf >> 1][2 + (nf & 1)]);
        }
    }

    if (MODE == 0) {
#pragma unroll
        for (int mi = 0; mi < 4; mi++) {
            int gr0 = row0 + m0 + mi * 16 + lg;
#pragma unroll
            for (int nf = 0; nf < 8; nf++) {
                int gc = col0 + n0 + nf * 8 + lt * 2;
                float bx = 0.f, by = 0.f;
                if (bias) { bx = bias[gc]; by = bias[gc + 1]; }
                size_t g0 = (size_t)gr0 * Nfull + gc;
                size_t g1 = g0 + (size_t)8 * Nfull;
                float2 v0 = make_float2(acc[mi][nf][0] + bx, acc[mi][nf][1] + by);
                float2 v1 = make_float2(acc[mi][nf][2] + bx, acc[mi][nf][3] + by);
                if (Cinit) {
                    float2 c0v = *(const float2*)(Cinit + g0);
                    float2 c1v = *(const float2*)(Cinit + g1);
                    v0.x += c0v.x; v0.y += c0v.y;
                    v1.x += c1v.x; v1.y += c1v.y;
                }
                *(float2*)(Cout + g0) = v0;
                *(float2*)(Cout + g1) = v1;
            }
        }
    } else {
        const int p = lt & 1;
#pragma unroll
        for (int mi = 0; mi < 4; mi++) {
            int gr0 = row0 + m0 + mi * 16 + lg;
#pragma unroll
            for (int nf = 0; nf < 8; nf++) {
                int gc = col0 + n0 + nf * 8 + lt * 2;
                float v0 = acc[mi][nf][0], v1 = acc[mi][nf][1];
                float v2 = acc[mi][nf][2], v3 = acc[mi][nf][3];
                if (bias) {
                    float bx = bias[gc], by = bias[gc + 1];
                    v0 += bx; v1 += by; v2 += bx; v3 += by;
                }
                if (Cinit) {
                    size_t g0 = (size_t)gr0 * Nfull + gc;
                    size_t g1 = g0 + (size_t)8 * Nfull;
                    float2 c0v = *(const float2*)(Cinit + g0);
                    float2 c1v = *(const float2*)(Cinit + g1);
                    v0 += c0v.x; v1 += c0v.y; v2 += c1v.x; v3 += c1v.y;
                }
                float x0 = __shfl_xor_sync(0xffffffffu, v0, 1);
                float x1 = __shfl_xor_sync(0xffffffffu, v1, 1);
                float x2 = __shfl_xor_sync(0xffffffffu, v2, 1);
                float x3 = __shfl_xor_sync(0xffffffffu, v3, 1);
                float gi, gf, gg, go;
                if (p == 0) { gi = v0; gf = v1; gg = x0; go = x1; }
                else        { gi = x2; gf = x3; gg = v2; go = v3; }
                int row = gr0 + p * 8;
                int h   = gc >> 2;
                int ci  = row * D_ + h;
                float c_old = cstate[ci];
                float cn = sigmoidf_(gf) * c_old + sigmoidf_(gi) * tanhf(gg);
                float hn = sigmoidf_(go) * tanhf(cn);
                cstate[ci] = cn;
                __half hh = __float2half_rn(hn);
                hout[ci] = hh;
                if (feats) feats[((size_t)row * BAR_ + t) * D_ + h] = hh;
            }
        }
    }
}

// ---------------------------------------------------------------------------
// Launch
// ---------------------------------------------------------------------------
extern "C" void kernel_launch(void* const* d_in, const int* in_sizes, int n_in,
                              void* d_out, int out_size) {
    const float* z       = (const float*)d_in[0];
    const float* gamma   = (const float*)d_in[1];
    const float* beta    = (const float*)d_in[2];
    const float* W_ih0   = (const float*)d_in[3];
    const float* W_hh0   = (const float*)d_in[4];
    const float* b_ih0   = (const float*)d_in[5];
    const float* b_hh0   = (const float*)d_in[6];
    const float* W_ih1   = (const float*)d_in[7];
    const float* W_hh1   = (const float*)d_in[8];
    const float* b_ih1   = (const float*)d_in[9];
    const float* b_hh1   = (const float*)d_in[10];
    const float* W_lin   = (const float*)d_in[11];
    const float* b_lin   = (const float*)d_in[12];
    float* out = (float*)d_out;

    __half *znh, *h0a, *h0b, *h1a, *h1b, *featsh;
    __half *wih0, *whh0, *wih1, *whh1, *wlin;
    float *c0, *c1, *x0p, *b0i, *b1i;
    cudaGetSymbolAddress((void**)&znh,   g_znh);
    cudaGetSymbolAddress((void**)&h0a,   g_h0a);
    cudaGetSymbolAddress((void**)&h0b,   g_h0b);
    cudaGetSymbolAddress((void**)&h1a,   g_h1a);
    cudaGetSymbolAddress((void**)&h1b,   g_h1b);
    cudaGetSymbolAddress((void**)&c0,    g_c0);
    cudaGetSymbolAddress((void**)&c1,    g_c1);
    cudaGetSymbolAddress((void**)&x0p,   g_x0p);
    cudaGetSymbolAddress((void**)&featsh,g_feats);
    cudaGetSymbolAddress((void**)&b0i,   g_b0i);
    cudaGetSymbolAddress((void**)&b1i,   g_b1i);
    cudaGetSymbolAddress((void**)&wih0,  g_wih0);
    cudaGetSymbolAddress((void**)&whh0,  g_whh0);
    cudaGetSymbolAddress((void**)&wih1,  g_wih1);
    cudaGetSymbolAddress((void**)&whh1,  g_whh1);
    cudaGetSymbolAddress((void**)&wlin,  g_wlin);

    cudaFuncSetAttribute(gemm_mma_kernel<0>,
                         cudaFuncAttributeMaxDynamicSharedMemorySize, DYN_BYTES);
    cudaFuncSetAttribute(gemm_mma_kernel<1>,
                         cudaFuncAttributeMaxDynamicSharedMemorySize, DYN_BYTES);

    // 1. BN + inits + interleaved bias/weight prep
    bn_stats_kernel<<<D_ / 32, dim3(32, 8)>>>(z, gamma, beta);
    bn_apply_init_kernel<<<(B_ * D_) / 512, 512>>>(z);
    bias_interleave_kernel<<<H4 / 256, 256>>>(b_ih0, b_hh0, b_ih1, b_hh1);
    weight_interleave_kernel<<<(H4 * 256) / 256, 256>>>(W_ih0, wih0);
    weight_interleave_kernel<<<(H4 * 256) / 256, 256>>>(W_hh0, whh0);
    weight_interleave_kernel<<<(H4 * 256) / 256, 256>>>(W_ih1, wih1);
    weight_interleave_kernel<<<(H4 * 256) / 256, 256>>>(W_hh1, whh1);
    weight_fp16_kernel<<<(D_ * D_ / 4) / 256, 256>>>(W_lin, wlin, D_ * D_ / 4);

    dim3 grid_layer(H4 / 256, B_ / 128);        // (16, 8) = 128 CTAs

    // 2. x0_proj (interleaved cols) = zn @ wih0^T + b0i
    gemm_mma_kernel<0><<<grid_layer, 256, DYN_BYTES>>>(
        znh, wih0, D_, nullptr, nullptr, 0, nullptr, b0i, x0p, H4,
        nullptr, nullptr, nullptr, 0);

    // 3. 32 recurrent steps, fused cell epilogues, ping-pong h buffers
    __half* h0cur = h0a; __half* h0nxt = h0b;
    __half* h1cur = h1a; __half* h1nxt = h1b;
    for (int t = 0; t < BAR_; t++) {
        gemm_mma_kernel<1><<<grid_layer, 256, DYN_BYTES>>>(
            h0cur, whh0, D_, nullptr, nullptr, 0, x0p, nullptr, nullptr, H4,
            c0, h0nxt, nullptr, 0);
        gemm_mma_kernel<1><<<grid_layer, 256, DYN_BYTES>>>(
            h0nxt, wih1, D_, h1cur, whh1, D_, nullptr, b1i, nullptr, H4,
            c1, h1nxt, featsh, t);
        __half* tmp;
        tmp = h0cur; h0cur = h0nxt; h0nxt = tmp;
        tmp = h1cur; h1cur = h1nxt; h1nxt = tmp;
    }

    // 4. out = feats(B*32, H) @ W_lin^T + b_lin
    dim3 grid_head(D_ / 256, (B_ * BAR_) / 128);   // (4, 256)
    gemm_mma_kernel<0><<<grid_head, 256, DYN_BYTES>>>(
        featsh, wlin, D_, nullptr, nullptr, 0, nullptr, b_lin, out, D_,
        nullptr, nullptr, nullptr, 0);
}

// round 11
// speedup vs baseline: 1.2220x; 1.2220x over previous
#include <cuda_runtime.h>
#include <cuda_fp16.h>
#include <math.h>
#include <cstdint>

// ---------------------------------------------------------------------------
// Problem constants
// ---------------------------------------------------------------------------
#define B_   1024
#define D_   1024
#define H4   4096
#define BAR_ 32
#define EPS_ 1e-5f

#define SMEM_SWIZZLE_128B(byte_offset) \
    ((byte_offset) ^ (((byte_offset) >> 3) & 0x70))

__device__ __forceinline__ uint32_t smem_to_u32(const void* smem_ptr) {
    uint32_t addr;
    asm("{ .reg .u64 tmp; cvta.to.shared.u64 tmp, %1; cvt.u32.u64 %0, tmp; }"
        : "=r"(addr) : "l"(smem_ptr));
    return addr;
}

__device__ __forceinline__ void ldsm_x4(uint32_t& r0, uint32_t& r1,
                                        uint32_t& r2, uint32_t& r3, uint32_t addr) {
    asm volatile("ldmatrix.sync.aligned.m8n8.x4.shared.b16 {%0,%1,%2,%3}, [%4];"
                 : "=r"(r0), "=r"(r1), "=r"(r2), "=r"(r3) : "r"(addr));
}

__device__ __forceinline__ void mma_fp16(float& d0, float& d1, float& d2, float& d3,
                                         uint32_t a0, uint32_t a1, uint32_t a2, uint32_t a3,
                                         uint32_t b0, uint32_t b1) {
    asm volatile(
        "mma.sync.aligned.m16n8k16.row.col.f32.f16.f16.f32 "
        "{%0,%1,%2,%3}, {%4,%5,%6,%7}, {%8,%9}, {%0,%1,%2,%3};"
        : "+f"(d0), "+f"(d1), "+f"(d2), "+f"(d3)
        : "r"(a0), "r"(a1), "r"(a2), "r"(a3), "r"(b0), "r"(b1));
}

__device__ __forceinline__ void cp_async16(uint32_t dst, const void* src) {
    asm volatile("cp.async.cg.shared.global [%0], [%1], 16;"
                 :: "r"(dst), "l"(src) : "memory");
}
#define CP_COMMIT() asm volatile("cp.async.commit_group;" ::: "memory")
#define CP_WAIT(N)  asm volatile("cp.async.wait_group %0;" :: "n"(N) : "memory")

__device__ __forceinline__ float sigmoidf_(float x) {
    return 1.f / (1.f + expf(-x));
}

// ---------------------------------------------------------------------------
// Scratch (device globals). h-states ping-pong across launches (race fix R8).
// ---------------------------------------------------------------------------
__device__ __half g_znh [B_ * D_];
__device__ __half g_h0a [B_ * D_];
__device__ __half g_h0b [B_ * D_];
__device__ __half g_h1a [B_ * D_];
__device__ __half g_h1b [B_ * D_];
__device__ float  g_c0  [B_ * D_];
__device__ float  g_c1  [B_ * D_];
__device__ float  g_x0p [B_ * H4];
__device__ __half g_feats[(size_t)B_ * BAR_ * D_];
__device__ float  g_scale[D_];
__device__ float  g_shift[D_];
__device__ float  g_b0i [H4];
__device__ float  g_b1i [H4];
__device__ __half g_wih0[H4 * D_];
__device__ __half g_whh0[H4 * D_];
__device__ __half g_wih1[H4 * D_];
__device__ __half g_whh1[H4 * D_];
__device__ __half g_wlin[D_ * D_];

// ---------------------------------------------------------------------------
// Prep kernels (unchanged)
// ---------------------------------------------------------------------------
__global__ void bn_stats_kernel(const float* __restrict__ z,
                                const float* __restrict__ gamma,
                                const float* __restrict__ beta) {
    __shared__ float ssum[8][32];
    __shared__ float ssq [8][32];
    int col = blockIdx.x * 32 + threadIdx.x;
    float s = 0.f, q = 0.f;
    for (int r = threadIdx.y; r < B_; r += 8) {
        float v = z[(size_t)r * D_ + col];
        s += v; q += v * v;
    }
    ssum[threadIdx.y][threadIdx.x] = s;
    ssq [threadIdx.y][threadIdx.x] = q;
    __syncthreads();
    if (threadIdx.y == 0) {
#pragma unroll
        for (int y = 1; y < 8; y++) { s += ssum[y][threadIdx.x]; q += ssq[y][threadIdx.x]; }
        float mean = s * (1.f / (float)B_);
        float var  = q * (1.f / (float)B_) - mean * mean;
        float sc   = gamma[col] * rsqrtf(var + EPS_);
        g_scale[col] = sc;
        g_shift[col] = beta[col] - mean * sc;
    }
}

__global__ void bn_apply_init_kernel(const float* __restrict__ z) {
    int idx = blockIdx.x * blockDim.x + threadIdx.x;
    int col = idx & (D_ - 1);
    float v = z[idx] * g_scale[col] + g_shift[col];
    __half vh = __float2half_rn(v);
    g_znh[idx] = vh;
    g_h0a[idx] = vh; g_h1a[idx] = vh;
    float vr = __half2float(vh);
    g_c0[idx] = vr;  g_c1[idx] = vr;
}

__global__ void bias_interleave_kernel(const float* __restrict__ b_ih0,
                                       const float* __restrict__ b_hh0,
                                       const float* __restrict__ b_ih1,
                                       const float* __restrict__ b_hh1) {
    int j = blockIdx.x * blockDim.x + threadIdx.x;
    if (j < H4) {
        int g = j & 3, h = j >> 2;
        g_b0i[j] = b_ih0[g * D_ + h] + b_hh0[g * D_ + h];
        g_b1i[j] = b_ih1[g * D_ + h] + b_hh1[g * D_ + h];
    }
}

__global__ void weight_interleave_kernel(const float* __restrict__ src,
                                         __half* __restrict__ dst) {
    int j = blockIdx.x * blockDim.x + threadIdx.x;
    int nr = j >> 8;
    int k4 = j & 255;
    int r_old = (nr & 3) * D_ + (nr >> 2);
    float4 v = *(const float4*)(src + (size_t)r_old * D_ + k4 * 4);
    __half2* d = (__half2*)(dst + (size_t)nr * D_ + k4 * 4);
    d[0] = __floats2half2_rn(v.x, v.y);
    d[1] = __floats2half2_rn(v.z, v.w);
}

__global__ void weight_fp16_kernel(const float* __restrict__ src,
                                   __half* __restrict__ dst, int n4) {
    int i = blockIdx.x * blockDim.x + threadIdx.x;
    if (i < n4) {
        float4 v = ((const float4*)src)[i];
        __half2* d = (__half2*)(dst + (size_t)i * 4);
        d[0] = __floats2half2_rn(v.x, v.y);
        d[1] = __floats2half2_rn(v.z, v.w);
    }
}

// ---------------------------------------------------------------------------
// fp16 mma.sync GEMM — R8 shape + ldmatrix + 3-stage pipeline.
// CTA tile 128x128, K-chunk 64 fp16. 8 warps (2Mx4N), warp tile 64x32.
// occ 2 (96KB smem/CTA, 2x96 <= 228KB).
// MODE 0: Cout(fp32) = bias? + Cinit? + A1@B1^T (+A2@B2^T)
// MODE 1: fused LSTM cell epilogue (gate-interleaved cols; hout != A1/A2!)
// smem per stage: A 16KB @ +0, B 16KB @ +16K; stage stride 32KB; 3 stages.
// ---------------------------------------------------------------------------
#define TK_ 64
#define STAGE_BYTES 32768u
#define DYN_BYTES (3u * 32768u + 1024u)

template<int MODE>
__global__ __launch_bounds__(256, 2)
void gemm_mma_kernel(const __half* __restrict__ A1, const __half* __restrict__ B1, int K1,
                     const __half* __restrict__ A2, const __half* __restrict__ B2, int K2,
                     const float* __restrict__ Cinit, const float* __restrict__ bias,
                     float* __restrict__ Cout, int Nfull,
                     float* __restrict__ cstate, __half* __restrict__ hout,
                     __half* __restrict__ feats, int t) {
    extern __shared__ char dyn_smem[];
    uint32_t raw  = smem_to_u32(dyn_smem);
    uint32_t base = (raw + 1023u) & ~1023u;

    const int tid  = threadIdx.x;
    const int wid  = tid >> 5;
    const int lane = tid & 31;
    const int lg   = lane >> 2;
    const int lt   = lane & 3;
    const int wm   = wid >> 2;          // 0..1 (M)
    const int wn   = wid & 3;           // 0..3 (N)
    const int row0 = blockIdx.y * 128;
    const int col0 = blockIdx.x * 128;
    const int m0   = wm * 64;
    const int n0   = wn * 32;

    // ldmatrix lane decomposition
    const uint32_t li   = lane & 7;
    const uint32_t jm8  = ((lane >> 3) & 1) * 8;
    const uint32_t jk16 = (lane >> 4) * 16;
    const uint32_t i16  = li << 4;
    const uint32_t aRow = (uint32_t)(m0 + jm8 + li) * 128;
    const uint32_t bRow = (uint32_t)(n0 + jm8 + li) * 128;

    const int lr0 = tid >> 3;           // loader row base (0..31)
    const int lc  = tid & 7;            // loader 16B column

    float acc[4][4][4];
#pragma unroll
    for (int mi = 0; mi < 4; mi++)
#pragma unroll
        for (int ni = 0; ni < 4; ni++)
#pragma unroll
            for (int r = 0; r < 4; r++) acc[mi][ni][r] = 0.f;

    const int nk = (K1 + K2) / TK_;

    auto load_chunk = [&](int kc, int st) {
        const __half* Ag; const __half* Bg; int kk, ldk;
        int k0 = kc * TK_;
        if (k0 < K1) { Ag = A1; Bg = B1; kk = k0;      ldk = K1; }
        else         { Ag = A2; Bg = B2; kk = k0 - K1; ldk = K2; }
        uint32_t sa = base + (uint32_t)st * STAGE_BYTES;
        uint32_t sb = sa + 16384u;
#pragma unroll
        for (int i = 0; i < 4; i++) {
            int r = lr0 + i * 32;
            cp_async16(sa + SMEM_SWIZZLE_128B(r * 128 + lc * 16),
                       Ag + (size_t)(row0 + r) * ldk + kk + lc * 8);
            cp_async16(sb + SMEM_SWIZZLE_128B(r * 128 + lc * 16),
                       Bg + (size_t)(col0 + r) * ldk + kk + lc * 8);
        }
        CP_COMMIT();
    };

    load_chunk(0, 0);
    if (nk > 1) load_chunk(1, 1);

    for (int k = 0; k < nk; k++) {
        if (k + 1 < nk) { CP_WAIT(1); } else { CP_WAIT(0); }
        __syncthreads();
        if (k + 2 < nk) load_chunk(k + 2, (k + 2) % 3);

        uint32_t sa = base + (uint32_t)(k % 3) * STAGE_BYTES;
        uint32_t sb = sa + 16384u;
#pragma unroll
        for (int ks = 0; ks < 4; ks++) {
            uint32_t kcol = ((uint32_t)(ks * 32) + jk16) ^ i16;
            uint32_t a[4][4];
#pragma unroll
            for (int mi = 0; mi < 4; mi++)
                ldsm_x4(a[mi][0], a[mi][1], a[mi][2], a[mi][3],
                        sa + aRow + (uint32_t)mi * 2048 + kcol);
            uint32_t b[2][4];
#pragma unroll
            for (int ni2 = 0; ni2 < 2; ni2++)
                ldsm_x4(b[ni2][0], b[ni2][1], b[ni2][2], b[ni2][3],
                        sb + bRow + (uint32_t)ni2 * 2048 + kcol);
#pragma unroll
            for (int mi = 0; mi < 4; mi++)
#pragma unroll
                for (int ni = 0; ni < 4; ni++)
                    mma_fp16(acc[mi][ni][0], acc[mi][ni][1],
                             acc[mi][ni][2], acc[mi][ni][3],
                             a[mi][0], a[mi][1], a[mi][2], a[mi][3],
                             b[ni >> 1][ni & 1], b[ni >> 1][2 + (ni & 1)]);
        }
    }

    if (MODE == 0) {
#pragma unroll
        for (int mi = 0; mi < 4; mi++) {
            int gr0 = row0 + m0 + mi * 16 + lg;
#pragma unroll
            for (int ni = 0; ni < 4; ni++) {
                int gc = col0 + n0 + ni * 8 + lt * 2;
                float bx = 0.f, by = 0.f;
                if (bias) { bx = bias[gc]; by = bias[gc + 1]; }
                size_t g0 = (size_t)gr0 * Nfull + gc;
                size_t g1 = g0 + (size_t)8 * Nfull;
                float2 v0 = make_float2(acc[mi][ni][0] + bx, acc[mi][ni][1] + by);
                float2 v1 = make_float2(acc[mi][ni][2] + bx, acc[mi][ni][3] + by);
                if (Cinit) {
                    float2 c0v = *(const float2*)(Cinit + g0);
                    float2 c1v = *(const float2*)(Cinit + g1);
                    v0.x += c0v.x; v0.y += c0v.y;
                    v1.x += c1v.x; v1.y += c1v.y;
                }
                *(float2*)(Cout + g0) = v0;
                *(float2*)(Cout + g1) = v1;
            }
        }
    } else {
        const int p = lt & 1;
#pragma unroll
        for (int mi = 0; mi < 4; mi++) {
            int gr0 = row0 + m0 + mi * 16 + lg;
#pragma unroll
            for (int ni = 0; ni < 4; ni++) {
                int gc = col0 + n0 + ni * 8 + lt * 2;
                float v0 = acc[mi][ni][0], v1 = acc[mi][ni][1];
                float v2 = acc[mi][ni][2], v3 = acc[mi][ni][3];
                if (bias) {
                    float bx = bias[gc], by = bias[gc + 1];
                    v0 += bx; v1 += by; v2 += bx; v3 += by;
                }
                if (Cinit) {
                    size_t g0 = (size_t)gr0 * Nfull + gc;
                    size_t g1 = g0 + (size_t)8 * Nfull;
                    float2 c0v = *(const float2*)(Cinit + g0);
                    float2 c1v = *(const float2*)(Cinit + g1);
                    v0 += c0v.x; v1 += c0v.y; v2 += c1v.x; v3 += c1v.y;
                }
                float x0 = __shfl_xor_sync(0xffffffffu, v0, 1);
                float x1 = __shfl_xor_sync(0xffffffffu, v1, 1);
                float x2 = __shfl_xor_sync(0xffffffffu, v2, 1);
                float x3 = __shfl_xor_sync(0xffffffffu, v3, 1);
                float gi, gf, gg, go;
                if (p == 0) { gi = v0; gf = v1; gg = x0; go = x1; }
                else        { gi = x2; gf = x3; gg = v2; go = v3; }
                int row = gr0 + p * 8;
                int h   = gc >> 2;
                int ci  = row * D_ + h;
                float c_old = cstate[ci];
                float cn = sigmoidf_(gf) * c_old + sigmoidf_(gi) * tanhf(gg);
                float hn = sigmoidf_(go) * tanhf(cn);
                cstate[ci] = cn;
                __half hh = __float2half_rn(hn);
                hout[ci] = hh;
                if (feats) feats[((size_t)row * BAR_ + t) * D_ + h] = hh;
            }
        }
    }
}

// ---------------------------------------------------------------------------
// Launch
// ---------------------------------------------------------------------------
extern "C" void kernel_launch(void* const* d_in, const int* in_sizes, int n_in,
                              void* d_out, int out_size) {
    const float* z       = (const float*)d_in[0];
    const float* gamma   = (const float*)d_in[1];
    const float* beta    = (const float*)d_in[2];
    const float* W_ih0   = (const float*)d_in[3];
    const float* W_hh0   = (const float*)d_in[4];
    const float* b_ih0   = (const float*)d_in[5];
    const float* b_hh0   = (const float*)d_in[6];
    const float* W_ih1   = (const float*)d_in[7];
    const float* W_hh1   = (const float*)d_in[8];
    const float* b_ih1   = (const float*)d_in[9];
    const float* b_hh1   = (const float*)d_in[10];
    const float* W_lin   = (const float*)d_in[11];
    const float* b_lin   = (const float*)d_in[12];
    float* out = (float*)d_out;

    __half *znh, *h0a, *h0b, *h1a, *h1b, *featsh;
    __half *wih0, *whh0, *wih1, *whh1, *wlin;
    float *c0, *c1, *x0p, *b0i, *b1i;
    cudaGetSymbolAddress((void**)&znh,   g_znh);
    cudaGetSymbolAddress((void**)&h0a,   g_h0a);
    cudaGetSymbolAddress((void**)&h0b,   g_h0b);
    cudaGetSymbolAddress((void**)&h1a,   g_h1a);
    cudaGetSymbolAddress((void**)&h1b,   g_h1b);
    cudaGetSymbolAddress((void**)&c0,    g_c0);
    cudaGetSymbolAddress((void**)&c1,    g_c1);
    cudaGetSymbolAddress((void**)&x0p,   g_x0p);
    cudaGetSymbolAddress((void**)&featsh,g_feats);
    cudaGetSymbolAddress((void**)&b0i,   g_b0i);
    cudaGetSymbolAddress((void**)&b1i,   g_b1i);
    cudaGetSymbolAddress((void**)&wih0,  g_wih0);
    cudaGetSymbolAddress((void**)&whh0,  g_whh0);
    cudaGetSymbolAddress((void**)&wih1,  g_wih1);
    cudaGetSymbolAddress((void**)&whh1,  g_whh1);
    cudaGetSymbolAddress((void**)&wlin,  g_wlin);

    cudaFuncSetAttribute(gemm_mma_kernel<0>,
                         cudaFuncAttributeMaxDynamicSharedMemorySize, DYN_BYTES);
    cudaFuncSetAttribute(gemm_mma_kernel<1>,
                         cudaFuncAttributeMaxDynamicSharedMemorySize, DYN_BYTES);

    // 1. BN + inits + interleaved bias/weight prep
    bn_stats_kernel<<<D_ / 32, dim3(32, 8)>>>(z, gamma, beta);
    bn_apply_init_kernel<<<(B_ * D_) / 512, 512>>>(z);
    bias_interleave_kernel<<<H4 / 256, 256>>>(b_ih0, b_hh0, b_ih1, b_hh1);
    weight_interleave_kernel<<<(H4 * 256) / 256, 256>>>(W_ih0, wih0);
    weight_interleave_kernel<<<(H4 * 256) / 256, 256>>>(W_hh0, whh0);
    weight_interleave_kernel<<<(H4 * 256) / 256, 256>>>(W_ih1, wih1);
    weight_interleave_kernel<<<(H4 * 256) / 256, 256>>>(W_hh1, whh1);
    weight_fp16_kernel<<<(D_ * D_ / 4) / 256, 256>>>(W_lin, wlin, D_ * D_ / 4);

    dim3 grid_layer(H4 / 128, B_ / 128);        // (32, 8) = 256 CTAs

    // 2. x0_proj (interleaved cols) = zn @ wih0^T + b0i
    gemm_mma_kernel<0><<<grid_layer, 256, DYN_BYTES>>>(
        znh, wih0, D_, nullptr, nullptr, 0, nullptr, b0i, x0p, H4,
        nullptr, nullptr, nullptr, 0);

    // 3. 32 recurrent steps, fused cell epilogues, ping-pong h buffers
    __half* h0cur = h0a; __half* h0nxt = h0b;
    __half* h1cur = h1a; __half* h1nxt = h1b;
    for (int t = 0; t < BAR_; t++) {
        gemm_mma_kernel<1><<<grid_layer, 256, DYN_BYTES>>>(
            h0cur, whh0, D_, nullptr, nullptr, 0, x0p, nullptr, nullptr, H4,
            c0, h0nxt, nullptr, 0);
        gemm_mma_kernel<1><<<grid_layer, 256, DYN_BYTES>>>(
            h0nxt, wih1, D_, h1cur, whh1, D_, nullptr, b1i, nullptr, H4,
            c1, h1nxt, featsh, t);
        __half* tmp;
        tmp = h0cur; h0cur = h0nxt; h0nxt = tmp;
        tmp = h1cur; h1cur = h1nxt; h1nxt = tmp;
    }

    // 4. out = feats(B*32, H) @ W_lin^T + b_lin
    dim3 grid_head(D_ / 128, (B_ * BAR_) / 128);   // (8, 256)
    gemm_mma_kernel<0><<<grid_head, 256, DYN_BYTES>>>(
        featsh, wlin, D_, nullptr, nullptr, 0, nullptr, b_lin, out, D_,
        nullptr, nullptr, nullptr, 0);
}

// round 12
// speedup vs baseline: 1.3388x; 1.0956x over previous
#include <cuda_runtime.h>
#include <cuda_fp16.h>
#include <math.h>
#include <cstdint>

// ---------------------------------------------------------------------------
// Problem constants
// ---------------------------------------------------------------------------
#define B_   1024
#define D_   1024
#define H4   4096
#define BAR_ 32
#define EPS_ 1e-5f

#define SMEM_SWIZZLE_128B(byte_offset) \
    ((byte_offset) ^ (((byte_offset) >> 3) & 0x70))

__device__ __forceinline__ uint32_t smem_to_u32(const void* smem_ptr) {
    uint32_t addr;
    asm("{ .reg .u64 tmp; cvta.to.shared.u64 tmp, %1; cvt.u32.u64 %0, tmp; }"
        : "=r"(addr) : "l"(smem_ptr));
    return addr;
}

__device__ __forceinline__ void ldsm_x4(uint32_t& r0, uint32_t& r1,
                                        uint32_t& r2, uint32_t& r3, uint32_t addr) {
    asm volatile("ldmatrix.sync.aligned.m8n8.x4.shared.b16 {%0,%1,%2,%3}, [%4];"
                 : "=r"(r0), "=r"(r1), "=r"(r2), "=r"(r3) : "r"(addr));
}

__device__ __forceinline__ void mma_fp16(float& d0, float& d1, float& d2, float& d3,
                                         uint32_t a0, uint32_t a1, uint32_t a2, uint32_t a3,
                                         uint32_t b0, uint32_t b1) {
    asm volatile(
        "mma.sync.aligned.m16n8k16.row.col.f32.f16.f16.f32 "
        "{%0,%1,%2,%3}, {%4,%5,%6,%7}, {%8,%9}, {%0,%1,%2,%3};"
        : "+f"(d0), "+f"(d1), "+f"(d2), "+f"(d3)
        : "r"(a0), "r"(a1), "r"(a2), "r"(a3), "r"(b0), "r"(b1));
}

__device__ __forceinline__ void cp_async16(uint32_t dst, const void* src) {
    asm volatile("cp.async.cg.shared.global [%0], [%1], 16;"
                 :: "r"(dst), "l"(src) : "memory");
}
#define CP_COMMIT() asm volatile("cp.async.commit_group;" ::: "memory")
#define CP_WAIT(N)  asm volatile("cp.async.wait_group %0;" :: "n"(N) : "memory")

__device__ __forceinline__ float sigmoidf_(float x) {
    return 1.f / (1.f + expf(-x));
}

// ---------------------------------------------------------------------------
// Scratch (device globals). h-states ping-pong across launches (race fix R8).
// ---------------------------------------------------------------------------
__device__ __half g_znh [B_ * D_];
__device__ __half g_h0a [B_ * D_];
__device__ __half g_h0b [B_ * D_];
__device__ __half g_h1a [B_ * D_];
__device__ __half g_h1b [B_ * D_];
__device__ float  g_c0  [B_ * D_];
__device__ float  g_c1  [B_ * D_];
__device__ float  g_x0p [B_ * H4];
__device__ __half g_feats[(size_t)B_ * BAR_ * D_];
__device__ float  g_scale[D_];
__device__ float  g_shift[D_];
__device__ float  g_b0i [H4];
__device__ float  g_b1i [H4];
__device__ __half g_wih0[H4 * D_];
__device__ __half g_whh0[H4 * D_];
__device__ __half g_wih1[H4 * D_];
__device__ __half g_whh1[H4 * D_];
__device__ __half g_wlin[D_ * D_];

// ---------------------------------------------------------------------------
// Prep kernels (unchanged)
// ---------------------------------------------------------------------------
__global__ void bn_stats_kernel(const float* __restrict__ z,
                                const float* __restrict__ gamma,
                                const float* __restrict__ beta) {
    __shared__ float ssum[8][32];
    __shared__ float ssq [8][32];
    int col = blockIdx.x * 32 + threadIdx.x;
    float s = 0.f, q = 0.f;
    for (int r = threadIdx.y; r < B_; r += 8) {
        float v = z[(size_t)r * D_ + col];
        s += v; q += v * v;
    }
    ssum[threadIdx.y][threadIdx.x] = s;
    ssq [threadIdx.y][threadIdx.x] = q;
    __syncthreads();
    if (threadIdx.y == 0) {
#pragma unroll
        for (int y = 1; y < 8; y++) { s += ssum[y][threadIdx.x]; q += ssq[y][threadIdx.x]; }
        float mean = s * (1.f / (float)B_);
        float var  = q * (1.f / (float)B_) - mean * mean;
        float sc   = gamma[col] * rsqrtf(var + EPS_);
        g_scale[col] = sc;
        g_shift[col] = beta[col] - mean * sc;
    }
}

__global__ void bn_apply_init_kernel(const float* __restrict__ z) {
    int idx = blockIdx.x * blockDim.x + threadIdx.x;
    int col = idx & (D_ - 1);
    float v = z[idx] * g_scale[col] + g_shift[col];
    __half vh = __float2half_rn(v);
    g_znh[idx] = vh;
    g_h0a[idx] = vh; g_h1a[idx] = vh;
    float vr = __half2float(vh);
    g_c0[idx] = vr;  g_c1[idx] = vr;
}

__global__ void bias_interleave_kernel(const float* __restrict__ b_ih0,
                                       const float* __restrict__ b_hh0,
                                       const float* __restrict__ b_ih1,
                                       const float* __restrict__ b_hh1) {
    int j = blockIdx.x * blockDim.x + threadIdx.x;
    if (j < H4) {
        int g = j & 3, h = j >> 2;
        g_b0i[j] = b_ih0[g * D_ + h] + b_hh0[g * D_ + h];
        g_b1i[j] = b_ih1[g * D_ + h] + b_hh1[g * D_ + h];
    }
}

__global__ void weight_interleave_kernel(const float* __restrict__ src,
                                         __half* __restrict__ dst) {
    int j = blockIdx.x * blockDim.x + threadIdx.x;
    int nr = j >> 8;
    int k4 = j & 255;
    int r_old = (nr & 3) * D_ + (nr >> 2);
    float4 v = *(const float4*)(src + (size_t)r_old * D_ + k4 * 4);
    __half2* d = (__half2*)(dst + (size_t)nr * D_ + k4 * 4);
    d[0] = __floats2half2_rn(v.x, v.y);
    d[1] = __floats2half2_rn(v.z, v.w);
}

__global__ void weight_fp16_kernel(const float* __restrict__ src,
                                   __half* __restrict__ dst, int n4) {
    int i = blockIdx.x * blockDim.x + threadIdx.x;
    if (i < n4) {
        float4 v = ((const float4*)src)[i];
        __half2* d = (__half2*)(dst + (size_t)i * 4);
        d[0] = __floats2half2_rn(v.x, v.y);
        d[1] = __floats2half2_rn(v.z, v.w);
    }
}

// ---------------------------------------------------------------------------
// fp16 mma.sync GEMM — CTA tile 128x128, K-chunk 64, 8 warps (2Mx4N),
// warp tile 64x32, ldmatrix.x4 loads, 3-stage cp.async pipeline, occ 2.
// MODE 0: Cout(fp32) = bias? + Cinit? + A1@B1^T (+A2@B2^T)
// MODE 1: fused LSTM cell epilogue (gate-interleaved cols; hout != A1/A2!)
// ---------------------------------------------------------------------------
#define TK_ 64
#define STAGE_BYTES 32768u
#define DYN_BYTES (3u * 32768u + 1024u)

template<int MODE>
__global__ __launch_bounds__(256, 2)
void gemm_mma_kernel(const __half* __restrict__ A1, const __half* __restrict__ B1, int K1,
                     const __half* __restrict__ A2, const __half* __restrict__ B2, int K2,
                     const float* __restrict__ Cinit, const float* __restrict__ bias,
                     float* __restrict__ Cout, int Nfull,
                     float* __restrict__ cstate, __half* __restrict__ hout,
                     __half* __restrict__ feats, int t) {
    extern __shared__ char dyn_smem[];
    uint32_t raw  = smem_to_u32(dyn_smem);
    uint32_t base = (raw + 1023u) & ~1023u;

    const int tid  = threadIdx.x;
    const int wid  = tid >> 5;
    const int lane = tid & 31;
    const int lg   = lane >> 2;
    const int lt   = lane & 3;
    const int wm   = wid >> 2;
    const int wn   = wid & 3;
    const int row0 = blockIdx.y * 128;
    const int col0 = blockIdx.x * 128;
    const int m0   = wm * 64;
    const int n0   = wn * 32;

    const uint32_t li   = lane & 7;
    const uint32_t jm8  = ((lane >> 3) & 1) * 8;
    const uint32_t jk16 = (lane >> 4) * 16;
    const uint32_t i16  = li << 4;
    const uint32_t aRow = (uint32_t)(m0 + jm8 + li) * 128;
    const uint32_t bRow = (uint32_t)(n0 + jm8 + li) * 128;

    const int lr0 = tid >> 3;
    const int lc  = tid & 7;

    float acc[4][4][4];
#pragma unroll
    for (int mi = 0; mi < 4; mi++)
#pragma unroll
        for (int ni = 0; ni < 4; ni++)
#pragma unroll
            for (int r = 0; r < 4; r++) acc[mi][ni][r] = 0.f;

    const int nk = (K1 + K2) / TK_;

    auto load_chunk = [&](int kc, int st) {
        const __half* Ag; const __half* Bg; int kk, ldk;
        int k0 = kc * TK_;
        if (k0 < K1) { Ag = A1; Bg = B1; kk = k0;      ldk = K1; }
        else         { Ag = A2; Bg = B2; kk = k0 - K1; ldk = K2; }
        uint32_t sa = base + (uint32_t)st * STAGE_BYTES;
        uint32_t sb = sa + 16384u;
#pragma unroll
        for (int i = 0; i < 4; i++) {
            int r = lr0 + i * 32;
            cp_async16(sa + SMEM_SWIZZLE_128B(r * 128 + lc * 16),
                       Ag + (size_t)(row0 + r) * ldk + kk + lc * 8);
            cp_async16(sb + SMEM_SWIZZLE_128B(r * 128 + lc * 16),
                       Bg + (size_t)(col0 + r) * ldk + kk + lc * 8);
        }
        CP_COMMIT();
    };

    load_chunk(0, 0);
    if (nk > 1) load_chunk(1, 1);

    for (int k = 0; k < nk; k++) {
        if (k + 1 < nk) { CP_WAIT(1); } else { CP_WAIT(0); }
        __syncthreads();
        if (k + 2 < nk) load_chunk(k + 2, (k + 2) % 3);

        uint32_t sa = base + (uint32_t)(k % 3) * STAGE_BYTES;
        uint32_t sb = sa + 16384u;
#pragma unroll
        for (int ks = 0; ks < 4; ks++) {
            uint32_t kcol = ((uint32_t)(ks * 32) + jk16) ^ i16;
            uint32_t a[4][4];
#pragma unroll
            for (int mi = 0; mi < 4; mi++)
                ldsm_x4(a[mi][0], a[mi][1], a[mi][2], a[mi][3],
                        sa + aRow + (uint32_t)mi * 2048 + kcol);
            uint32_t b[2][4];
#pragma unroll
            for (int ni2 = 0; ni2 < 2; ni2++)
                ldsm_x4(b[ni2][0], b[ni2][1], b[ni2][2], b[ni2][3],
                        sb + bRow + (uint32_t)ni2 * 2048 + kcol);
#pragma unroll
            for (int mi = 0; mi < 4; mi++)
#pragma unroll
                for (int ni = 0; ni < 4; ni++)
                    mma_fp16(acc[mi][ni][0], acc[mi][ni][1],
                             acc[mi][ni][2], acc[mi][ni][3],
                             a[mi][0], a[mi][1], a[mi][2], a[mi][3],
                             b[ni >> 1][ni & 1], b[ni >> 1][2 + (ni & 1)]);
        }
    }

    if (MODE == 0) {
#pragma unroll
        for (int mi = 0; mi < 4; mi++) {
            int gr0 = row0 + m0 + mi * 16 + lg;
#pragma unroll
            for (int ni = 0; ni < 4; ni++) {
                int gc = col0 + n0 + ni * 8 + lt * 2;
                float bx = 0.f, by = 0.f;
                if (bias) { bx = bias[gc]; by = bias[gc + 1]; }
                size_t g0 = (size_t)gr0 * Nfull + gc;
                size_t g1 = g0 + (size_t)8 * Nfull;
                float2 v0 = make_float2(acc[mi][ni][0] + bx, acc[mi][ni][1] + by);
                float2 v1 = make_float2(acc[mi][ni][2] + bx, acc[mi][ni][3] + by);
                if (Cinit) {
                    float2 c0v = *(const float2*)(Cinit + g0);
                    float2 c1v = *(const float2*)(Cinit + g1);
                    v0.x += c0v.x; v0.y += c0v.y;
                    v1.x += c1v.x; v1.y += c1v.y;
                }
                *(float2*)(Cout + g0) = v0;
                *(float2*)(Cout + g1) = v1;
            }
        }
    } else {
        const int p = lt & 1;
#pragma unroll
        for (int mi = 0; mi < 4; mi++) {
            int gr0 = row0 + m0 + mi * 16 + lg;
#pragma unroll
            for (int ni = 0; ni < 4; ni++) {
                int gc = col0 + n0 + ni * 8 + lt * 2;
                float v0 = acc[mi][ni][0], v1 = acc[mi][ni][1];
                float v2 = acc[mi][ni][2], v3 = acc[mi][ni][3];
                if (bias) {
                    float bx = bias[gc], by = bias[gc + 1];
                    v0 += bx; v1 += by; v2 += bx; v3 += by;
                }
                if (Cinit) {
                    size_t g0 = (size_t)gr0 * Nfull + gc;
                    size_t g1 = g0 + (size_t)8 * Nfull;
                    float2 c0v = *(const float2*)(Cinit + g0);
                    float2 c1v = *(const float2*)(Cinit + g1);
                    v0 += c0v.x; v1 += c0v.y; v2 += c1v.x; v3 += c1v.y;
                }
                float x0 = __shfl_xor_sync(0xffffffffu, v0, 1);
                float x1 = __shfl_xor_sync(0xffffffffu, v1, 1);
                float x2 = __shfl_xor_sync(0xffffffffu, v2, 1);
                float x3 = __shfl_xor_sync(0xffffffffu, v3, 1);
                float gi, gf, gg, go;
                if (p == 0) { gi = v0; gf = v1; gg = x0; go = x1; }
                else        { gi = x2; gf = x3; gg = v2; go = v3; }
                int row = gr0 + p * 8;
                int h   = gc >> 2;
                int ci  = row * D_ + h;
                float c_old = cstate[ci];
                float cn = sigmoidf_(gf) * c_old + sigmoidf_(gi) * tanhf(gg);
                float hn = sigmoidf_(go) * tanhf(cn);
                cstate[ci] = cn;
                __half hh = __float2half_rn(hn);
                hout[ci] = hh;
                if (feats) feats[((size_t)row * BAR_ + t) * D_ + h] = hh;
            }
        }
    }
}

// ---------------------------------------------------------------------------
// Launch: dual-stream overlap.
// Dependency DAG: L1(t) <- L0(t);  L0(t) <- L0(t-1), L1(t-2).
// L0(t+1) runs concurrently with L1(t) (fills its wave tail).
// The L1(t-2) edge is exactly the anti-dependency that keeps the 2-buffer
// h0 ping-pong safe (h0^t's last reader is L1(t-1), before L0(t+1) writes).
// ---------------------------------------------------------------------------
extern "C" void kernel_launch(void* const* d_in, const int* in_sizes, int n_in,
                              void* d_out, int out_size) {
    const float* z       = (const float*)d_in[0];
    const float* gamma   = (const float*)d_in[1];
    const float* beta    = (const float*)d_in[2];
    const float* W_ih0   = (const float*)d_in[3];
    const float* W_hh0   = (const float*)d_in[4];
    const float* b_ih0   = (const float*)d_in[5];
    const float* b_hh0   = (const float*)d_in[6];
    const float* W_ih1   = (const float*)d_in[7];
    const float* W_hh1   = (const float*)d_in[8];
    const float* b_ih1   = (const float*)d_in[9];
    const float* b_hh1   = (const float*)d_in[10];
    const float* W_lin   = (const float*)d_in[11];
    const float* b_lin   = (const float*)d_in[12];
    float* out = (float*)d_out;

    __half *znh, *h0a, *h0b, *h1a, *h1b, *featsh;
    __half *wih0, *whh0, *wih1, *whh1, *wlin;
    float *c0, *c1, *x0p, *b0i, *b1i;
    cudaGetSymbolAddress((void**)&znh,   g_znh);
    cudaGetSymbolAddress((void**)&h0a,   g_h0a);
    cudaGetSymbolAddress((void**)&h0b,   g_h0b);
    cudaGetSymbolAddress((void**)&h1a,   g_h1a);
    cudaGetSymbolAddress((void**)&h1b,   g_h1b);
    cudaGetSymbolAddress((void**)&c0,    g_c0);
    cudaGetSymbolAddress((void**)&c1,    g_c1);
    cudaGetSymbolAddress((void**)&x0p,   g_x0p);
    cudaGetSymbolAddress((void**)&featsh,g_feats);
    cudaGetSymbolAddress((void**)&b0i,   g_b0i);
    cudaGetSymbolAddress((void**)&b1i,   g_b1i);
    cudaGetSymbolAddress((void**)&wih0,  g_wih0);
    cudaGetSymbolAddress((void**)&whh0,  g_whh0);
    cudaGetSymbolAddress((void**)&wih1,  g_wih1);
    cudaGetSymbolAddress((void**)&whh1,  g_whh1);
    cudaGetSymbolAddress((void**)&wlin,  g_wlin);

    cudaFuncSetAttribute(gemm_mma_kernel<0>,
                         cudaFuncAttributeMaxDynamicSharedMemorySize, DYN_BYTES);
    cudaFuncSetAttribute(gemm_mma_kernel<1>,
                         cudaFuncAttributeMaxDynamicSharedMemorySize, DYN_BYTES);

    // One-time host resources (no device memory involved). Created before
    // the first (correctness) call completes, so graph capture sees them.
    static cudaStream_t s2 = nullptr;
    static cudaEvent_t  eA = nullptr;
    static cudaEvent_t  eB0 = nullptr, eB1 = nullptr;
    if (!s2) {
        cudaStreamCreateWithFlags(&s2, cudaStreamNonBlocking);
        cudaEventCreateWithFlags(&eA,  cudaEventDisableTiming);
        cudaEventCreateWithFlags(&eB0, cudaEventDisableTiming);
        cudaEventCreateWithFlags(&eB1, cudaEventDisableTiming);
    }
    cudaEvent_t eB[2] = {eB0, eB1};
    cudaStream_t s0 = 0;   // legacy default stream (captured by harness)

    // 1. BN + inits + interleaved bias/weight prep (S0)
    bn_stats_kernel<<<D_ / 32, dim3(32, 8)>>>(z, gamma, beta);
    bn_apply_init_kernel<<<(B_ * D_) / 512, 512>>>(z);
    bias_interleave_kernel<<<H4 / 256, 256>>>(b_ih0, b_hh0, b_ih1, b_hh1);
    weight_interleave_kernel<<<(H4 * 256) / 256, 256>>>(W_ih0, wih0);
    weight_interleave_kernel<<<(H4 * 256) / 256, 256>>>(W_hh0, whh0);
    weight_interleave_kernel<<<(H4 * 256) / 256, 256>>>(W_ih1, wih1);
    weight_interleave_kernel<<<(H4 * 256) / 256, 256>>>(W_hh1, whh1);
    weight_fp16_kernel<<<(D_ * D_ / 4) / 256, 256>>>(W_lin, wlin, D_ * D_ / 4);

    dim3 grid_layer(H4 / 128, B_ / 128);        // (32, 8) = 256 CTAs

    // 2. x0_proj (interleaved cols) = zn @ wih0^T + b0i  (S0)
    gemm_mma_kernel<0><<<grid_layer, 256, DYN_BYTES>>>(
        znh, wih0, D_, nullptr, nullptr, 0, nullptr, b0i, x0p, H4,
        nullptr, nullptr, nullptr, 0);

    // 3. 32 recurrent steps. L0 chain on S0, L1 chain on s2, overlapped.
    __half* h0cur = h0a; __half* h0nxt = h0b;
    __half* h1cur = h1a; __half* h1nxt = h1b;
    for (int t = 0; t < BAR_; t++) {
        if (t >= 2) cudaStreamWaitEvent(s0, eB[t & 1], 0);   // L0(t) <- L1(t-2)
        gemm_mma_kernel<1><<<grid_layer, 256, DYN_BYTES, s0>>>(
            h0cur, whh0, D_, nullptr, nullptr, 0, x0p, nullptr, nullptr, H4,
            c0, h0nxt, nullptr, 0);
        cudaEventRecord(eA, s0);
        cudaStreamWaitEvent(s2, eA, 0);                      // L1(t) <- L0(t)
        gemm_mma_kernel<1><<<grid_layer, 256, DYN_BYTES, s2>>>(
            h0nxt, wih1, D_, h1cur, whh1, D_, nullptr, b1i, nullptr, H4,
            c1, h1nxt, featsh, t);
        cudaEventRecord(eB[t & 1], s2);
        __half* tmp;
        tmp = h0cur; h0cur = h0nxt; h0nxt = tmp;
        tmp = h1cur; h1cur = h1nxt; h1nxt = tmp;
    }
    // join: head GEMM needs the full feats from L1(31)
    cudaStreamWaitEvent(s0, eB[(BAR_ - 1) & 1], 0);

    // 4. out = feats(B*32, H) @ W_lin^T + b_lin  (S0)
    dim3 grid_head(D_ / 128, (B_ * BAR_) / 128);   // (8, 256)
    gemm_mma_kernel<0><<<grid_head, 256, DYN_BYTES, s0>>>(
        featsh, wlin, D_, nullptr, nullptr, 0, nullptr, b_lin, out, D_,
        nullptr, nullptr, nullptr, 0);
}